// round 7
// baseline (speedup 1.0000x reference)
#include <cuda_runtime.h>

// LSTM: B=4096, H=256, T=256, input_size=1, then sigmoid(h_last @ w_out + b_out).
// Persistent per-CTA design: each CTA owns 32 batch rows through all 256 steps.
// Recurrent GEMM uses packed fma.rn.f32x2 (2 FMA/lane/instr) with W_hh
// pre-transposed AND duplicated in gmem so no per-k packing MOVs are needed.

#define T_LEN   256
#define H_DIM   256
#define B_TOT   4096
#define COND_N  192
#define PRED_N  64
#define B_TILE  32
#define SROW    40        // padded row stride (floats) for h/c smem
#define NTHR    512

// Duplicated transpose of w_hh: g_wt[k*2048 + 2*j] = g_wt[k*2048 + 2*j + 1] = w_hh[j*256 + k]
__device__ __align__(16) float g_wt[T_LEN * 2048];

__global__ void transpose_dup_kernel(const float* __restrict__ w_hh) {
    int idx = blockIdx.x * blockDim.x + threadIdx.x;   // over 1024*256 elements
    if (idx >= 1024 * 256) return;
    int j = idx >> 8;
    int k = idx & 255;
    float v = w_hh[idx];                                // w_hh[j*256 + k], coalesced read
    *(float2*)&g_wt[k * 2048 + 2 * j] = make_float2(v, v);
}

__device__ __forceinline__ void fma2(unsigned long long& d,
                                     unsigned long long a,
                                     unsigned long long b) {
    asm("fma.rn.f32x2 %0, %1, %2, %0;" : "+l"(d) : "l"(a), "l"(b));
}
__device__ __forceinline__ float ulo(unsigned long long u) {
    return __uint_as_float((unsigned)u);
}
__device__ __forceinline__ float uhi(unsigned long long u) {
    return __uint_as_float((unsigned)(u >> 32));
}
__device__ __forceinline__ float sigf(float x) {
    return __fdividef(1.f, 1.f + __expf(-x));
}
__device__ __forceinline__ float tanh_acc(float x) {
    x = fminf(fmaxf(x, -15.f), 15.f);
    float e = __expf(-2.f * x);
    return __fdividef(1.f - e, 1.f + e);
}

__global__ void __launch_bounds__(NTHR, 1) lstm_kernel(
    const float* __restrict__ cd,     const float* __restrict__ pred,
    const float* __restrict__ w_ih,   const float* __restrict__ b_ih,
    const float* __restrict__ b_hh,   const float* __restrict__ w_out,
    const float* __restrict__ b_out,  float* __restrict__ out)
{
    extern __shared__ float sm[];
    float*  hs = sm;                          // [H_DIM][SROW]  h, transposed [k][b]
    float*  cs = hs + H_DIM * SROW;           // [H_DIM][SROW]  c
    float*  xs = cs + H_DIM * SROW;           // [T_LEN][B_TILE] input sequence
    float2* wb = (float2*)(xs + T_LEN * B_TILE); // [4H] (w_ih[j], b_ih[j]+b_hh[j])

    const int tid   = threadIdx.x;
    const int lane  = tid & 31;
    const int warp  = tid >> 5;
    const int bgrp  = lane & 3;     // 4 b-groups per warp -> 64B-contig h reads
    const int jgl   = lane >> 2;    // 8 j-groups per warp -> 128B-contig w reads
    const int b0    = bgrp * 8;
    const int jg    = warp * 8 + jgl;   // 0..127
    const int m0    = jg * 2;           // hidden-unit pair owned by this thread
    const int bbase = blockIdx.x * B_TILE;

    // ---- init smem: h0=c0=0, gather input sequence, fuse biases ----
    for (int i = tid; i < H_DIM * SROW; i += NTHR) { hs[i] = 0.f; cs[i] = 0.f; }
    for (int i = tid; i < T_LEN * B_TILE; i += NTHR) {
        int t = i >> 5, bl = i & 31;
        int gb = bbase + bl;
        xs[i] = (t < COND_N) ? cd[gb * COND_N + t] : pred[gb * PRED_N + (t - COND_N)];
    }
    for (int j = tid; j < 4 * H_DIM; j += NTHR)
        wb[j] = make_float2(w_ih[j], b_ih[j] + b_hh[j]);
    __syncthreads();

    const ulonglong2* wt_u = (const ulonglong2*)g_wt;  // 512 ulonglong2 per k-row

    for (int t = 0; t < T_LEN; t++) {
        // acc[gate][mi][bpair] : packed (b even, b odd) fp32 pair
        unsigned long long acc[4][2][4];
        #pragma unroll
        for (int g = 0; g < 4; g++)
            #pragma unroll
            for (int mi = 0; mi < 2; mi++)
                #pragma unroll
                for (int bp = 0; bp < 4; bp++) acc[g][mi][bp] = 0ull;

        // ---- gates += h @ W_hh^T  (the 65k-cycle FMA2 mainloop) ----
        #pragma unroll 2
        for (int k = 0; k < H_DIM; k++) {
            ulonglong2 h01 = *(const ulonglong2*)(hs + k * SROW + b0);     // b0..b0+3
            ulonglong2 h23 = *(const ulonglong2*)(hs + k * SROW + b0 + 4); // b0+4..b0+7
            #pragma unroll
            for (int g = 0; g < 4; g++) {
                // .x = (w_m0, w_m0), .y = (w_m0+1, w_m0+1)  -- pre-duplicated in gmem
                ulonglong2 w = wt_u[k * 512 + g * 128 + jg];
                fma2(acc[g][0][0], w.x, h01.x);
                fma2(acc[g][0][1], w.x, h01.y);
                fma2(acc[g][0][2], w.x, h23.x);
                fma2(acc[g][0][3], w.x, h23.y);
                fma2(acc[g][1][0], w.y, h01.x);
                fma2(acc[g][1][1], w.y, h01.y);
                fma2(acc[g][1][2], w.y, h23.x);
                fma2(acc[g][1][3], w.y, h23.y);
            }
        }

        // ---- elementwise LSTM cell update ----
        float xv[8];
        #pragma unroll
        for (int bi = 0; bi < 8; bi++) xv[bi] = xs[t * B_TILE + b0 + bi];

        float hv[2][8];
        #pragma unroll
        for (int mi = 0; mi < 2; mi++) {
            float2 wbi = wb[0 * H_DIM + m0 + mi];
            float2 wbf = wb[1 * H_DIM + m0 + mi];
            float2 wbg = wb[2 * H_DIM + m0 + mi];
            float2 wbo = wb[3 * H_DIM + m0 + mi];
            #pragma unroll
            for (int bp = 0; bp < 4; bp++) {
                #pragma unroll
                for (int hf = 0; hf < 2; hf++) {
                    int bi = 2 * bp + hf;
                    float ai = hf ? uhi(acc[0][mi][bp]) : ulo(acc[0][mi][bp]);
                    float af = hf ? uhi(acc[1][mi][bp]) : ulo(acc[1][mi][bp]);
                    float ag = hf ? uhi(acc[2][mi][bp]) : ulo(acc[2][mi][bp]);
                    float ao = hf ? uhi(acc[3][mi][bp]) : ulo(acc[3][mi][bp]);
                    float x = xv[bi];
                    float ig = sigf    (ai + x * wbi.x + wbi.y);
                    float fg = sigf    (af + x * wbf.x + wbf.y);
                    float gg = tanh_acc(ag + x * wbg.x + wbg.y);
                    float og = sigf    (ao + x * wbo.x + wbo.y);
                    int ci = (m0 + mi) * SROW + b0 + bi;   // private per thread
                    float c = fg * cs[ci] + ig * gg;
                    cs[ci] = c;
                    hv[mi][bi] = og * tanh_acc(c);
                }
            }
        }

        __syncthreads();   // everyone done READING old h
        #pragma unroll
        for (int mi = 0; mi < 2; mi++)
            #pragma unroll
            for (int bp = 0; bp < 4; bp++)
                *(float2*)(hs + (m0 + mi) * SROW + b0 + 2 * bp) =
                    make_float2(hv[mi][2 * bp], hv[mi][2 * bp + 1]);
        __syncthreads();   // new h visible for next step
    }

    // ---- output head: sigmoid(h_last @ w_out + b_out) ----
    if (tid < B_TILE) {
        float a = b_out[0];
        #pragma unroll 8
        for (int m = 0; m < H_DIM; m++) a += hs[m * SROW + tid] * w_out[m];
        out[bbase + tid] = __fdividef(1.f, 1.f + __expf(-a));
    }
}

extern "C" void kernel_launch(void* const* d_in, const int* in_sizes, int n_in,
                              void* d_out, int out_size) {
    const float* cd    = (const float*)d_in[0];
    const float* pred  = (const float*)d_in[1];
    const float* w_ih  = (const float*)d_in[2];
    const float* w_hh  = (const float*)d_in[3];
    const float* b_ih  = (const float*)d_in[4];
    const float* b_hh  = (const float*)d_in[5];
    const float* w_out = (const float*)d_in[6];
    const float* b_out = (const float*)d_in[7];
    float* out = (float*)d_out;

    (void)in_sizes; (void)n_in; (void)out_size;

    // One-time (per launch) duplicated transpose of W_hh into __device__ scratch.
    transpose_dup_kernel<<<1024, 256>>>(w_hh);

    const int smem_bytes = (2 * H_DIM * SROW + T_LEN * B_TILE) * 4 + 4 * H_DIM * 8; // 122880
    cudaFuncSetAttribute(lstm_kernel,
                         cudaFuncAttributeMaxDynamicSharedMemorySize, smem_bytes);
    lstm_kernel<<<B_TOT / B_TILE, NTHR, smem_bytes>>>(
        cd, pred, w_ih, b_ih, b_hh, w_out, b_out, out);
}

// round 11
// speedup vs baseline: 1.0378x; 1.0378x over previous
#include <cuda_runtime.h>

// LSTM: B=4096, H=256, T=256, input_size=1; out = sigmoid(h_last @ w_out + b_out).
// Persistent per-CTA design: each CTA owns 32 batch rows for all 256 steps.
// R8 change: accumulators packed over UNIT pairs -> weights load non-duplicated
// (2 LDG.128/thread/k instead of 4), h duplicated in SMEM (bank-swizzled),
// double-buffered h (1 barrier/step), c state in registers.

#define T_LEN   256
#define H_DIM   256
#define B_TOT   4096
#define COND_N  192
#define PRED_N  64
#define B_TILE  32
#define NTHR    512
#define HROW    64                 // floats per duplicated-h row (32 batches x2)
#define HD_SZ   (H_DIM * HROW)     // 16384 floats per h buffer

// Transposed, gate-interleaved W_hh:
// g_wt[k*1024 + jg*8 + g*2 + u] = w_hh[(g*256 + jg*2 + u)*256 + k]
__device__ __align__(16) float g_wt[H_DIM * 1024];

__global__ void transpose_kernel(const float* __restrict__ w_hh) {
    int idx = blockIdx.x * blockDim.x + threadIdx.x;   // over 1024*256, coalesced read
    if (idx >= 1024 * 256) return;
    int row = idx >> 8;          // g*256 + m
    int k   = idx & 255;
    int g   = row >> 8;
    int m   = row & 255;
    g_wt[k * 1024 + (m >> 1) * 8 + g * 2 + (m & 1)] = w_hh[idx];
}

__device__ __forceinline__ void fma2(unsigned long long& d,
                                     unsigned long long a,
                                     unsigned long long b) {
    asm("fma.rn.f32x2 %0, %1, %2, %0;" : "+l"(d) : "l"(a), "l"(b));
}
__device__ __forceinline__ float ulo(unsigned long long u) {
    return __uint_as_float((unsigned)u);
}
__device__ __forceinline__ float uhi(unsigned long long u) {
    return __uint_as_float((unsigned)(u >> 32));
}
__device__ __forceinline__ float sigf(float x) {
    return __fdividef(1.f, 1.f + __expf(-x));
}
__device__ __forceinline__ float tanh_acc(float x) {
    x = fminf(fmaxf(x, -15.f), 15.f);
    float e = __expf(-2.f * x);
    return __fdividef(1.f - e, 1.f + e);
}

__global__ void __launch_bounds__(NTHR, 1) lstm_kernel(
    const float* __restrict__ cd,     const float* __restrict__ pred,
    const float* __restrict__ w_ih,   const float* __restrict__ b_ih,
    const float* __restrict__ b_hh,   const float* __restrict__ w_out,
    const float* __restrict__ b_out,  float* __restrict__ out)
{
    extern __shared__ float sm[];
    float*  hd = sm;                              // 2 x [H_DIM][HROW] dup-h buffers
    float*  xs = sm + 2 * HD_SZ;                  // [T_LEN][B_TILE]
    float2* wb = (float2*)(xs + T_LEN * B_TILE);  // [4H]: (w_ih[j], b_ih[j]+b_hh[j])

    const int tid   = threadIdx.x;
    const int lane  = tid & 31;
    const int warp  = tid >> 5;
    const int bgrp  = lane & 3;          // batch group (8 batches each)
    const int jgl   = lane >> 2;         // 8 unit-pair groups per warp
    const int b0    = bgrp * 8;
    const int jg    = warp * 8 + jgl;    // 0..127 unit-pair index
    const int m0    = jg * 2;            // hidden units (m0, m0+1) owned
    const int bbase = blockIdx.x * B_TILE;

    // ---- init: h buffer 0 = 0, gather input sequence, fuse biases ----
    for (int i = tid; i < HD_SZ; i += NTHR) hd[i] = 0.f;
    for (int i = tid; i < T_LEN * B_TILE; i += NTHR) {
        int t = i >> 5, bl = i & 31;
        int gb = bbase + bl;
        xs[i] = (t < COND_N) ? cd[gb * COND_N + t] : pred[gb * PRED_N + (t - COND_N)];
    }
    for (int j = tid; j < 4 * H_DIM; j += NTHR)
        wb[j] = make_float2(w_ih[j], b_ih[j] + b_hh[j]);
    __syncthreads();

    float c[2][8];
    #pragma unroll
    for (int mi = 0; mi < 2; mi++)
        #pragma unroll
        for (int bi = 0; bi < 8; bi++) c[mi][bi] = 0.f;

    for (int t = 0; t < T_LEN; t++) {
        const float* hr = hd + (t & 1) * HD_SZ;
        float*       hw = hd + ((t + 1) & 1) * HD_SZ;

        // acc[gate][bi] packed as (unit m0, unit m0+1) fp32 pair
        unsigned long long acc[4][8];
        #pragma unroll
        for (int g = 0; g < 4; g++)
            #pragma unroll
            for (int bi = 0; bi < 8; bi++) acc[g][bi] = 0ull;

        // ---- gates += h @ W_hh^T : 32 FFMA2 + 2 LDG.128 + 4 LDS.128 per k ----
        #pragma unroll 2
        for (int k = 0; k < H_DIM; k++) {
            const ulonglong2* hp =
                (const ulonglong2*)(hr + k * HROW + bgrp * 4);
            // swizzled dup-h: load i gives dup pairs for batches b0+2i, b0+2i+1
            ulonglong2 hA = hp[0];    // bi 0,1
            ulonglong2 hB = hp[4];    // bi 2,3   (+16 floats)
            ulonglong2 hC = hp[8];    // bi 4,5   (+32 floats)
            ulonglong2 hD = hp[12];   // bi 6,7   (+48 floats)
            const ulonglong2* wp =
                (const ulonglong2*)(g_wt + k * 1024 + jg * 8);
            ulonglong2 w01 = wp[0];   // .x = gate i pair, .y = gate f pair
            ulonglong2 w23 = wp[1];   // .x = gate g pair, .y = gate o pair

            unsigned long long hdup[8] = {hA.x, hA.y, hB.x, hB.y,
                                          hC.x, hC.y, hD.x, hD.y};
            unsigned long long wg[4] = {w01.x, w01.y, w23.x, w23.y};
            #pragma unroll
            for (int g = 0; g < 4; g++)
                #pragma unroll
                for (int bi = 0; bi < 8; bi++)
                    fma2(acc[g][bi], wg[g], hdup[bi]);
        }

        // ---- elementwise LSTM cell update ----
        float xv[8];
        #pragma unroll
        for (int bi = 0; bi < 8; bi++) xv[bi] = xs[t * B_TILE + b0 + bi];

        #pragma unroll
        for (int mi = 0; mi < 2; mi++) {
            float2 wbi = wb[0 * H_DIM + m0 + mi];
            float2 wbf = wb[1 * H_DIM + m0 + mi];
            float2 wbg = wb[2 * H_DIM + m0 + mi];
            float2 wbo = wb[3 * H_DIM + m0 + mi];
            #pragma unroll
            for (int bi = 0; bi < 8; bi++) {
                float ai = mi ? uhi(acc[0][bi]) : ulo(acc[0][bi]);
                float af = mi ? uhi(acc[1][bi]) : ulo(acc[1][bi]);
                float ag = mi ? uhi(acc[2][bi]) : ulo(acc[2][bi]);
                float ao = mi ? uhi(acc[3][bi]) : ulo(acc[3][bi]);
                float x  = xv[bi];
                float ig = sigf    (ai + x * wbi.x + wbi.y);
                float fg = sigf    (af + x * wbf.x + wbf.y);
                float gg = tanh_acc(ag + x * wbg.x + wbg.y);
                float og = sigf    (ao + x * wbo.x + wbo.y);
                float cn = fg * c[mi][bi] + ig * gg;
                c[mi][bi] = cn;
                float hv = og * tanh_acc(cn);
                // swizzled dup write: pos(b) = i*16 + g*4 + r*2, b = 8g+2i+r
                int pos = ((bi >> 1) << 4) + (bgrp << 2) + ((bi & 1) << 1);
                *(float2*)(hw + (m0 + mi) * HROW + pos) = make_float2(hv, hv);
            }
        }

        __syncthreads();   // new h (other buffer) visible; old buffer reusable
    }

    // ---- output head: sigmoid(h_last @ w_out + b_out); h_last in buffer 0 ----
    if (tid < B_TILE) {
        int gq = tid >> 3, iq = (tid >> 1) & 3, rq = tid & 1;
        int pos = iq * 16 + gq * 4 + rq * 2;
        float a = b_out[0];
        #pragma unroll 8
        for (int m = 0; m < H_DIM; m++) a += hd[m * HROW + pos] * w_out[m];
        out[bbase + tid] = __fdividef(1.f, 1.f + __expf(-a));
    }
}

extern "C" void kernel_launch(void* const* d_in, const int* in_sizes, int n_in,
                              void* d_out, int out_size) {
    const float* cd    = (const float*)d_in[0];
    const float* pred  = (const float*)d_in[1];
    const float* w_ih  = (const float*)d_in[2];
    const float* w_hh  = (const float*)d_in[3];
    const float* b_ih  = (const float*)d_in[4];
    const float* b_hh  = (const float*)d_in[5];
    const float* w_out = (const float*)d_in[6];
    const float* b_out = (const float*)d_in[7];
    float* out = (float*)d_out;

    (void)in_sizes; (void)n_in; (void)out_size;

    transpose_kernel<<<1024, 256>>>(w_hh);

    const int smem_bytes = 2 * HD_SZ * 4 + T_LEN * B_TILE * 4 + 4 * H_DIM * 8; // 172032
    cudaFuncSetAttribute(lstm_kernel,
                         cudaFuncAttributeMaxDynamicSharedMemorySize, smem_bytes);
    lstm_kernel<<<B_TOT / B_TILE, NTHR, smem_bytes>>>(
        cd, pred, w_ih, b_ih, b_hh, w_out, b_out, out);
}